// round 11
// baseline (speedup 1.0000x reference)
#include <cuda_runtime.h>
#include <math.h>

#define Bq 4096
#define Sq 512
#define NT 256
#define NB 512
#define RPB 8
#define KST 76               // unified k: h[0:64) | x[64:75) | pad(75)
#define HBUFSZ (RPB*KST)     // 608 floats per buffer

typedef unsigned long long ull;

// shared layout (float offsets)
#define O_EX   0                     // ex [2 kh][8 r][256 g] = 4096
#define O_PRE  (O_EX + 4096)         // pre [8][256]          = 2048
#define O_HB   (O_PRE + 2048)        // 2 * [8][KST]          = 1216
#define O_WOUT (O_HB + 2*HBUFSZ)     // 128
#define O_SC   (O_WOUT + 128)        // 8
#define O_ISC  (O_SC + 8)            // 8
#define SM_TOTAL (O_ISC + 8)
#define SMEM_BYTES (SM_TOTAL*4)      // ~30 KB

__device__ __forceinline__ float sigf(float x){ return 1.0f/(1.0f+__expf(-x)); }
__device__ __forceinline__ float tanh_f(float x){ return 2.0f/(1.0f+__expf(-2.0f*x)) - 1.0f; }

__device__ __forceinline__ void ffma2(ull &d, ull a, ull b){
    asm("fma.rn.f32x2 %0, %1, %2, %0;" : "+l"(d) : "l"(a), "l"(b));
}
__device__ __forceinline__ float fold2(ull v){
    float2 f; asm("mov.b64 {%0,%1}, %2;" : "=f"(f.x), "=f"(f.y) : "l"(v));
    return f.x + f.y;
}
__device__ __forceinline__ ull pack2(float lo, float hi){
    ull v; asm("mov.b64 %0, {%1,%2};" : "=l"(v) : "f"(lo), "f"(hi));
    return v;
}

__global__ void __launch_bounds__(NT,2)
deepar_kernel(const float* __restrict__ target,
              const float* __restrict__ covar,
              const int*   __restrict__ cats,
              const float* __restrict__ scale,
              const float* __restrict__ e0,
              const float* __restrict__ e1,
              const float* __restrict__ e2,
              const float* __restrict__ e3,
              const float* __restrict__ w_ih,
              const float* __restrict__ w_hh,
              const float* __restrict__ bias,
              const float* __restrict__ w_out,
              const float* __restrict__ b_out,
              float* __restrict__ out)
{
    extern __shared__ float sm[];
    float* ex_s   = sm + O_EX;
    float* pre_s  = sm + O_PRE;
    float* hbuf   = sm + O_HB;
    float* wout_s = sm + O_WOUT;
    float* sc_s   = sm + O_SC;
    float* isc_s  = sm + O_ISC;
    float* sx_s   = sm + O_EX;       // alias: static_x [8][66], prologue only

    const int tid  = threadIdx.x;
    const int row0 = blockIdx.x * RPB;

    // ---- stage static_x [8][66] ----
    for (int e = tid; e < RPB*65; e += NT){
        int r = e / 65, j = e - r*65;
        int b = row0 + r;
        float v;
        if (j < 64){
            int tsel = j >> 4, jj = j & 15;
            int c = cats[b*4 + tsel];
            const float* et = (tsel==0)?e0:(tsel==1)?e1:(tsel==2)?e2:e3;
            v = et[c*16 + jj];
        } else {
            v = log1pf(scale[b]);
        }
        sx_s[r*66 + j] = v;
    }
    __syncthreads();

    // ---- thread map: gp = tid&127 (gates 2gp, 2gp+1), kh = tid>>7 ----
    const int gp = tid & 127;
    const int kh = tid >> 7;
    const int g0 = 2*gp, g1 = 2*gp + 1;

    // ---- pre[r][g] = bias + static_x @ w_ih[11:76] (exact fp32, one-time) ----
    {
        int pr  = tid >> 5;          // 0..7
        int pg8 = (tid & 31) * 8;
        float accp[8];
        #pragma unroll
        for (int j = 0; j < 8; j++) accp[j] = bias[pg8 + j];
        for (int k = 0; k < 65; k++){
            float xv = sx_s[pr*66 + k];
            const float* wr = w_ih + (11+k)*256 + pg8;
            #pragma unroll
            for (int j = 0; j < 8; j++) accp[j] = fmaf(xv, wr[j], accp[j]);
        }
        __syncthreads();   // sx reads done (ex_s alias safe to reuse)
        #pragma unroll
        for (int j = 0; j < 8; j++) pre_s[pr*256 + pg8 + j] = accp[j];
    }

    // ---- register weights: unified k halves [0,40) / [40,76) ----
    #define WU(k,g) ((k) < 64 ? w_hh[(k)*256 + (g)] : ((k) < 75 ? w_ih[((k)-64)*256 + (g)] : 0.0f))
    ull wA[20], wB[20];
    #pragma unroll
    for (int i = 0; i < 20; i++){ wA[i] = 0ull; wB[i] = 0ull; }
    if (kh == 0){
        #pragma unroll
        for (int i2 = 0; i2 < 10; i2++){
            int k = 4*i2;
            wA[2*i2]   = pack2(WU(k,  g0), WU(k+1,g0));
            wA[2*i2+1] = pack2(WU(k+2,g0), WU(k+3,g0));
            wB[2*i2]   = pack2(WU(k,  g1), WU(k+1,g1));
            wB[2*i2+1] = pack2(WU(k+2,g1), WU(k+3,g1));
        }
    } else {
        #pragma unroll
        for (int i2 = 0; i2 < 9; i2++){
            int k = 40 + 4*i2;
            wA[2*i2]   = pack2(WU(k,  g0), WU(k+1,g0));
            wA[2*i2+1] = pack2(WU(k+2,g0), WU(k+3,g0));
            wB[2*i2]   = pack2(WU(k,  g1), WU(k+1,g1));
            wB[2*i2+1] = pack2(WU(k+2,g1), WU(k+3,g1));
        }
    }
    #undef WU

    // ---- misc smem init ----
    if (tid < 128) wout_s[tid] = w_out[tid];
    if (tid < RPB){
        float s = scale[row0 + tid];
        sc_s[tid]  = s;
        isc_s[tid] = 1.0f / fmaxf(s, 1e-4f);
    }
    for (int i = tid; i < 2*HBUFSZ; i += NT) hbuf[i] = 0.0f;
    __syncthreads();

    // ---- x ownership: tid 0..95 -> (8 rows x 12 j) ----
    int xrow = 0, xj = 0, xb = 0;
    const bool xown = (tid < 96);
    float xreg = 0.0f;
    if (xown){
        xrow = tid / 12; xj = tid % 12; xb = row0 + xrow;
        float v = 0.0f;
        if (xj >= 1 && xj <= 10) v = covar[(xb*Sq + 0)*10 + (xj-1)];
        hbuf[1*HBUFSZ + xrow*KST + 64 + xj] = v;   // x(0)
    }
    // head: tid 96..111 -> (8 rows x 2)
    const bool hown = (tid >= 96) && (tid < 112);
    const int  hr_  = (tid - 96) >> 1;
    const int  hws  = tid & 1;
    // cell map: 2 cells/thread
    const int er  = tid >> 5;        // row 0..7
    const int ek2 = (tid & 31) * 2;  // cells ek2, ek2+1
    __syncthreads();

    float creg0 = 0.0f, creg1 = 0.0f;
    const int koff = 40*kh;

    for (int t = 0; t < Sq; t++){
        // ============ phase A: head(t-1), x prefetch, GEMM, ex store ============
        const float* hbb = hbuf + ((t+1)&1)*HBUFSZ;   // h(t-1) | x(t)

        if (hown && t > 0){
            const float* hr = hbb + hr_*KST;
            float a0=0.f,a1=0.f,a2=0.f,a3=0.f;
            #pragma unroll 8
            for (int k = 0; k < 64; k += 4){
                a0 = fmaf(hr[k],   wout_s[2*k     + hws], a0);
                a1 = fmaf(hr[k+1], wout_s[2*(k+1) + hws], a1);
                a2 = fmaf(hr[k+2], wout_s[2*(k+2) + hws], a2);
                a3 = fmaf(hr[k+3], wout_s[2*(k+3) + hws], a3);
            }
            float a = (a0+a1)+(a2+a3) + b_out[hws];
            float sp = (a > 15.0f) ? a : log1pf(__expf(a));
            sp += 1e-4f;
            int b = row0 + hr_;
            if (hws == 0) out[b*Sq + (t-1)] = sp * sc_s[hr_];
            else          out[Bq*Sq + b*Sq + (t-1)] = sp;
        }
        if (xown && t+1 < Sq){
            if (xj == 0)       xreg = target[xb*Sq + t] * isc_s[xrow];
            else if (xj <= 10) xreg = covar[(xb*Sq + t+1)*10 + (xj-1)];
            else               xreg = 0.0f;
        }

        ull acc[8][2];
        #pragma unroll
        for (int r = 0; r < 8; r++){ acc[r][0] = 0ull; acc[r][1] = 0ull; }

        const float* hbk = hbb + koff;
        if (kh == 0){
            #pragma unroll
            for (int i2 = 0; i2 < 10; i2++){
                #pragma unroll
                for (int r = 0; r < 8; r++){
                    ulonglong2 hv = *(const ulonglong2*)(hbk + r*KST + 4*i2);
                    ffma2(acc[r][0], hv.x, wA[2*i2]);
                    ffma2(acc[r][1], hv.x, wB[2*i2]);
                    ffma2(acc[r][0], hv.y, wA[2*i2+1]);
                    ffma2(acc[r][1], hv.y, wB[2*i2+1]);
                }
            }
        } else {
            #pragma unroll
            for (int i2 = 0; i2 < 9; i2++){
                #pragma unroll
                for (int r = 0; r < 8; r++){
                    ulonglong2 hv = *(const ulonglong2*)(hbk + r*KST + 4*i2);
                    ffma2(acc[r][0], hv.x, wA[2*i2]);
                    ffma2(acc[r][1], hv.x, wB[2*i2]);
                    ffma2(acc[r][0], hv.y, wA[2*i2+1]);
                    ffma2(acc[r][1], hv.y, wB[2*i2+1]);
                }
            }
        }
        // store partial gate pairs
        #pragma unroll
        for (int r = 0; r < 8; r++){
            *(float2*)(ex_s + (kh*8 + r)*256 + g0) =
                make_float2(fold2(acc[r][0]), fold2(acc[r][1]));
        }
        __syncthreads();

        // ============ phase B: cell (2 elements), h store, x store ============
        {
            float* hw = hbuf + (t&1)*HBUFSZ;
            const float* exl = ex_s + er*256 + ek2;
            const float* exh = ex_s + (8 + er)*256 + ek2;
            const float* ppl = pre_s + er*256 + ek2;
            float2 gi = make_float2(exl[0]   + exh[0]   + ppl[0],
                                    exl[1]   + exh[1]   + ppl[1]);
            float2 gf = make_float2(exl[64]  + exh[64]  + ppl[64],
                                    exl[65]  + exh[65]  + ppl[65]);
            float2 gg = make_float2(exl[128] + exh[128] + ppl[128],
                                    exl[129] + exh[129] + ppl[129]);
            float2 go = make_float2(exl[192] + exh[192] + ppl[192],
                                    exl[193] + exh[193] + ppl[193]);
            float i0 = sigf(gi.x), i1 = sigf(gi.y);
            float f0 = sigf(gf.x), f1 = sigf(gf.y);
            float G0 = tanh_f(gg.x), G1 = tanh_f(gg.y);
            float o0 = sigf(go.x), o1 = sigf(go.y);
            creg0 = fmaf(f0, creg0, i0*G0);
            creg1 = fmaf(f1, creg1, i1*G1);
            *(float2*)(hw + er*KST + ek2) =
                make_float2(o0*tanh_f(creg0), o1*tanh_f(creg1));
            if (xown) hw[xrow*KST + 64 + xj] = xreg;
        }
        __syncthreads();
    }

    // final head for t = Sq-1
    if (hown){
        const float* hr = hbuf + ((Sq-1)&1)*HBUFSZ + hr_*KST;
        float a0=0.f,a1=0.f,a2=0.f,a3=0.f;
        #pragma unroll 8
        for (int k = 0; k < 64; k += 4){
            a0 = fmaf(hr[k],   wout_s[2*k     + hws], a0);
            a1 = fmaf(hr[k+1], wout_s[2*(k+1) + hws], a1);
            a2 = fmaf(hr[k+2], wout_s[2*(k+2) + hws], a2);
            a3 = fmaf(hr[k+3], wout_s[2*(k+3) + hws], a3);
        }
        float a = (a0+a1)+(a2+a3) + b_out[hws];
        float sp = (a > 15.0f) ? a : log1pf(__expf(a));
        sp += 1e-4f;
        int b = row0 + hr_;
        if (hws == 0) out[b*Sq + (Sq-1)] = sp * sc_s[hr_];
        else          out[Bq*Sq + b*Sq + (Sq-1)] = sp;
    }
}

extern "C" void kernel_launch(void* const* d_in, const int* in_sizes, int n_in,
                              void* d_out, int out_size)
{
    (void)in_sizes; (void)n_in; (void)out_size;
    cudaFuncSetAttribute(deepar_kernel,
                         cudaFuncAttributeMaxDynamicSharedMemorySize, SMEM_BYTES);
    deepar_kernel<<<NB, NT, SMEM_BYTES>>>(
        (const float*)d_in[0],   // target
        (const float*)d_in[1],   // covariates
        (const int*)  d_in[2],   // static_cats
        (const float*)d_in[3],   // scale
        (const float*)d_in[4],   // emb0
        (const float*)d_in[5],   // emb1
        (const float*)d_in[6],   // emb2
        (const float*)d_in[7],   // emb3
        (const float*)d_in[8],   // w_ih
        (const float*)d_in[9],   // w_hh
        (const float*)d_in[10],  // bias
        (const float*)d_in[11],  // w_out
        (const float*)d_in[12],  // b_out
        (float*)d_out);
}

// round 12
// speedup vs baseline: 1.1266x; 1.1266x over previous
#include <cuda_runtime.h>
#include <math.h>

#define Bq 4096
#define Sq 512
#define NT 512
#define NB 128
#define RPB 32
#define KST 84               // h[0:64) | x[64:75) | pad → bank-clean rows
#define HBUFSZ (RPB*KST)     // 2688 floats per buffer

typedef unsigned long long ull;

// shared layout (float offsets)
#define O_WA   0                     // wa [40 kk][64 gt] float4 = 10240
#define O_WB   (O_WA + 10240)        // wb same                  = 10240
#define O_HB   (O_WB + 10240)        // 2 * [32][KST]            = 5376
#define O_WOUT (O_HB + 2*HBUFSZ)     // 128
#define O_SC   (O_WOUT + 128)
#define O_ISC  (O_SC + 32)
#define SM_TOTAL (O_ISC + 32)
#define SMEM_BYTES (SM_TOTAL*4)      // ~102 KB

__device__ __forceinline__ float sigf(float x){ return 1.0f/(1.0f+__expf(-x)); }
__device__ __forceinline__ float tanh_f(float x){ return 2.0f/(1.0f+__expf(-2.0f*x)) - 1.0f; }

__device__ __forceinline__ void ffma2(ull &d, ull a, ull b){
    asm("fma.rn.f32x2 %0, %1, %2, %0;" : "+l"(d) : "l"(a), "l"(b));
}
__device__ __forceinline__ float fold2(ull v){
    float2 f; asm("mov.b64 {%0,%1}, %2;" : "=f"(f.x), "=f"(f.y) : "l"(v));
    return f.x + f.y;
}
__device__ __forceinline__ void gbar(int id){
    asm volatile("bar.sync %0, 128;" :: "r"(id) : "memory");
}

__global__ void __launch_bounds__(NT,1)
deepar_kernel(const float* __restrict__ target,
              const float* __restrict__ covar,
              const int*   __restrict__ cats,
              const float* __restrict__ scale,
              const float* __restrict__ e0,
              const float* __restrict__ e1,
              const float* __restrict__ e2,
              const float* __restrict__ e3,
              const float* __restrict__ w_ih,
              const float* __restrict__ w_hh,
              const float* __restrict__ bias,
              const float* __restrict__ w_out,
              const float* __restrict__ b_out,
              float* __restrict__ out)
{
    extern __shared__ float sm[];
    float* wa_s   = sm + O_WA;
    float* wb_s   = sm + O_WB;
    float* hbuf   = sm + O_HB;
    float* wout_s = sm + O_WOUT;
    float* sc_s   = sm + O_SC;
    float* isc_s  = sm + O_ISC;
    float* sx_s   = sm + O_WA;     // alias: static_x [32][66], prologue only

    const int tid  = threadIdx.x;
    const int row0 = blockIdx.x * RPB;

    // ---- stage static_x [32][66] ----
    for (int e = tid; e < RPB*65; e += NT){
        int r = e / 65, j = e - r*65;
        int b = row0 + r;
        float v;
        if (j < 64){
            int tsel = j >> 4, jj = j & 15;
            int c = cats[b*4 + tsel];
            const float* et = (tsel==0)?e0:(tsel==1)?e1:(tsel==2)?e2:e3;
            v = et[c*16 + jj];
        } else {
            v = log1pf(scale[b]);
        }
        sx_s[r*66 + j] = v;
    }
    __syncthreads();

    // ---- mapping: group(128 thr)=grp owns 8 rows; warp = 16 gt x 2 kh ----
    const int grp   = tid >> 7;          // 0..3
    const int gLane = tid & 127;
    const int wg    = (tid >> 5) & 3;    // warp in group
    const int lane  = tid & 31;
    const int gl    = lane & 15;
    const int kh    = lane >> 4;         // k-half (in-warp!)
    const int gt    = wg*16 + gl;        // cell column 0..63
    const int rbase = grp * 8;
    const int kh4   = kh*4;              // my cell rows: rbase+kh4..+3
    const int oh4   = 4 - kh4;

    // ---- pre[j][tp] for my 4 cell rows (registers, one-time) ----
    float pre[4][4];
    {
        #pragma unroll
        for (int tp = 0; tp < 4; tp++){
            float bv = bias[tp*64 + gt];
            #pragma unroll
            for (int j = 0; j < 4; j++) pre[j][tp] = bv;
        }
        for (int k = 0; k < 65; k++){
            const float* wr = w_ih + (11+k)*256 + gt;
            float w0 = wr[0], w1 = wr[64], w2 = wr[128], w3 = wr[192];
            #pragma unroll
            for (int j = 0; j < 4; j++){
                float xv = sx_s[(rbase + kh4 + j)*66 + k];
                pre[j][0] = fmaf(xv, w0, pre[j][0]);
                pre[j][1] = fmaf(xv, w1, pre[j][1]);
                pre[j][2] = fmaf(xv, w2, pre[j][2]);
                pre[j][3] = fmaf(xv, w3, pre[j][3]);
            }
        }
    }
    __syncthreads();   // sx reads done; wa_s reusable

    // ---- pack weights [40 kk][64 gt]: wa={i:kpair,f:kpair}, wb={g:kpair,o:kpair} ----
    for (int idx = tid; idx < 40*64; idx += NT){
        int kk = idx >> 6, g = idx & 63;
        int k0 = 2*kk, k1 = 2*kk + 1;
        #define WK(k,c) ((k) < 64 ? w_hh[(k)*256 + (c)] : ((k) < 75 ? w_ih[((k)-64)*256 + (c)] : 0.0f))
        float4 a4, b4;
        a4.x = WK(k0, g);        a4.y = WK(k1, g);
        a4.z = WK(k0, 64 + g);   a4.w = WK(k1, 64 + g);
        b4.x = WK(k0, 128 + g);  b4.y = WK(k1, 128 + g);
        b4.z = WK(k0, 192 + g);  b4.w = WK(k1, 192 + g);
        #undef WK
        *(float4*)(wa_s + idx*4) = a4;
        *(float4*)(wb_s + idx*4) = b4;
    }
    if (tid < 128) wout_s[tid] = w_out[tid];
    if (tid < RPB){
        float s = scale[row0 + tid];
        sc_s[tid]  = s;
        isc_s[tid] = 1.0f / fmaxf(s, 1e-4f);
    }
    for (int i = tid; i < 2*HBUFSZ; i += NT) hbuf[i] = 0.0f;
    __syncthreads();

    // ---- x ownership: gLane 0..95 -> (8 rows x 12 j) per group ----
    int xrow = 0, xj = 0, xb = 0;
    const bool xown = (gLane < 96);
    float xreg = 0.0f;
    if (xown){
        xrow = rbase + gLane/12;
        xj   = gLane % 12;
        xb   = row0 + xrow;
        float v = 0.0f;
        if (xj >= 1 && xj <= 10) v = covar[(xb*Sq + 0)*10 + (xj-1)];
        hbuf[1*HBUFSZ + xrow*KST + 64 + xj] = v;   // x(0)
    }
    // head: gLane 96..111 -> (8 rows x 2)
    const bool hown = (gLane >= 96) && (gLane < 112);
    const int  hr_  = rbase + ((gLane - 96) >> 1);
    const int  hws  = gLane & 1;
    __syncthreads();

    const int barid = grp + 1;
    float creg[4] = {0,0,0,0};

    for (int t = 0; t < Sq; t++){
        gbar(barid);   // group-local: h(t-1)/x(t) rows visible
        const float* hb = hbuf + ((t+1)&1)*HBUFSZ;   // h(t-1) | x(t)

        // head for step t-1 (stable buffer)
        if (hown && t > 0){
            const float* hr = hb + hr_*KST;
            float a0=0.f,a1=0.f,a2=0.f,a3=0.f;
            #pragma unroll 8
            for (int k = 0; k < 64; k += 4){
                a0 = fmaf(hr[k],   wout_s[2*k     + hws], a0);
                a1 = fmaf(hr[k+1], wout_s[2*(k+1) + hws], a1);
                a2 = fmaf(hr[k+2], wout_s[2*(k+2) + hws], a2);
                a3 = fmaf(hr[k+3], wout_s[2*(k+3) + hws], a3);
            }
            float a = (a0+a1)+(a2+a3) + b_out[hws];
            float sp = (a > 15.0f) ? a : log1pf(__expf(a));
            sp += 1e-4f;
            int b = row0 + hr_;
            if (hws == 0) out[b*Sq + (t-1)] = sp * sc_s[hr_];
            else          out[Bq*Sq + b*Sq + (t-1)] = sp;
        }
        // prefetch x(t+1)
        if (xown && t+1 < Sq){
            if (xj == 0)       xreg = target[xb*Sq + t] * isc_s[xrow];
            else if (xj <= 10) xreg = covar[(xb*Sq + t+1)*10 + (xj-1)];
            else               xreg = 0.0f;
        }

        // ======= GEMM: 8 rows x 4 types over my k-half (kk2 = kh*10+i2) =======
        ull acc[8][4];
        #pragma unroll
        for (int r = 0; r < 8; r++)
            #pragma unroll
            for (int tp = 0; tp < 4; tp++) acc[r][tp] = 0ull;

        #pragma unroll
        for (int i2 = 0; i2 < 10; i2++){
            int kk2 = kh*10 + i2;
            ulonglong2 wa0 = *(const ulonglong2*)(wa_s + ((2*kk2  )*64 + gt)*4);
            ulonglong2 wb0 = *(const ulonglong2*)(wb_s + ((2*kk2  )*64 + gt)*4);
            ulonglong2 wa1 = *(const ulonglong2*)(wa_s + ((2*kk2+1)*64 + gt)*4);
            ulonglong2 wb1 = *(const ulonglong2*)(wb_s + ((2*kk2+1)*64 + gt)*4);
            #pragma unroll
            for (int r = 0; r < 8; r++){
                ulonglong2 hv = *(const ulonglong2*)(hb + (rbase+r)*KST + kk2*4);
                ffma2(acc[r][0], hv.x, wa0.x);
                ffma2(acc[r][1], hv.x, wa0.y);
                ffma2(acc[r][2], hv.x, wb0.x);
                ffma2(acc[r][3], hv.x, wb0.y);
                ffma2(acc[r][0], hv.y, wa1.x);
                ffma2(acc[r][1], hv.y, wa1.y);
                ffma2(acc[r][2], hv.y, wb1.x);
                ffma2(acc[r][3], hv.y, wb1.y);
            }
        }

        // ======= shuffle-fold + fused cell (my 4 rows), h/x store =======
        {
            float* hw = hbuf + (t&1)*HBUFSZ;
            #pragma unroll
            for (int j = 0; j < 4; j++){
                float g4[4];
                #pragma unroll
                for (int tp = 0; tp < 4; tp++){
                    float mine = fold2(acc[kh4 + j][tp]);
                    float send = fold2(acc[oh4 + j][tp]);
                    float got  = __shfl_xor_sync(0xffffffffu, send, 16);
                    g4[tp] = mine + got + pre[j][tp];
                }
                float i = sigf(g4[0]);
                float f = sigf(g4[1]);
                float g = tanh_f(g4[2]);
                float o = sigf(g4[3]);
                float c = fmaf(f, creg[j], i*g);
                creg[j] = c;
                hw[(rbase + kh4 + j)*KST + gt] = o * tanh_f(c);
            }
            if (xown) hw[xrow*KST + 64 + xj] = xreg;   // x(t+1)
        }
    }

    // final head for t = Sq-1
    gbar(barid);
    if (hown){
        const float* hr = hbuf + ((Sq-1)&1)*HBUFSZ + hr_*KST;
        float a0=0.f,a1=0.f,a2=0.f,a3=0.f;
        #pragma unroll 8
        for (int k = 0; k < 64; k += 4){
            a0 = fmaf(hr[k],   wout_s[2*k     + hws], a0);
            a1 = fmaf(hr[k+1], wout_s[2*(k+1) + hws], a1);
            a2 = fmaf(hr[k+2], wout_s[2*(k+2) + hws], a2);
            a3 = fmaf(hr[k+3], wout_s[2*(k+3) + hws], a3);
        }
        float a = (a0+a1)+(a2+a3) + b_out[hws];
        float sp = (a > 15.0f) ? a : log1pf(__expf(a));
        sp += 1e-4f;
        int b = row0 + hr_;
        if (hws == 0) out[b*Sq + (Sq-1)] = sp * sc_s[hr_];
        else          out[Bq*Sq + b*Sq + (Sq-1)] = sp;
    }
}

extern "C" void kernel_launch(void* const* d_in, const int* in_sizes, int n_in,
                              void* d_out, int out_size)
{
    (void)in_sizes; (void)n_in; (void)out_size;
    cudaFuncSetAttribute(deepar_kernel,
                         cudaFuncAttributeMaxDynamicSharedMemorySize, SMEM_BYTES);
    deepar_kernel<<<NB, NT, SMEM_BYTES>>>(
        (const float*)d_in[0],   // target
        (const float*)d_in[1],   // covariates
        (const int*)  d_in[2],   // static_cats
        (const float*)d_in[3],   // scale
        (const float*)d_in[4],   // emb0
        (const float*)d_in[5],   // emb1
        (const float*)d_in[6],   // emb2
        (const float*)d_in[7],   // emb3
        (const float*)d_in[8],   // w_ih
        (const float*)d_in[9],   // w_hh
        (const float*)d_in[10],  // bias
        (const float*)d_in[11],  // w_out
        (const float*)d_in[12],  // b_out
        (float*)d_out);
}